// round 7
// baseline (speedup 1.0000x reference)
#include <cuda_runtime.h>
#include <cuda_bf16.h>
#include <cstdint>

#define N_ROWS 4096
#define D_GRP  512
#define V_IN   16
#define U_MID  64
#define H_DIM  8192
#define GCHUNK 8          // groups per CTA
#define NROWT  32         // row tiles (N_ROWS/128)

#define LOG2E     1.4426950408889634f
#define INV_LN2   1.4426950408889634f
#define N_INV_LN2 (-1.4426950408889634f)
#define LN2F      0.6931471805599453f

// per-row-tile completion counters (zero-init; each run resets its own slot)
__device__ unsigned int g_tile_ctr[NROWT];

__device__ __forceinline__ float ex2f(float v) {
    float r; asm("ex2.approx.f32 %0, %1;" : "=f"(r) : "f"(v)); return r;
}

// pack two fp32 -> bf16x2
__device__ __forceinline__ uint32_t packbf2(float a, float b) {
    __nv_bfloat162 t = __floats2bfloat162_rn(a, b);
    return *reinterpret_cast<uint32_t*>(&t);
}
// split pair (a,b) into hi bf16x2 and exact-residual lo bf16x2
__device__ __forceinline__ void split2(float a, float b, uint32_t& hi, uint32_t& lo) {
    hi = packbf2(a, b);
    float ah = __uint_as_float(hi << 16);
    float bh = __uint_as_float(hi & 0xFFFF0000u);
    lo = packbf2(a - ah, b - bh);
}

// mma.m16n8k16 row.col bf16 -> fp32 accumulate in place
__device__ __forceinline__ void mma16816(float* c, const uint32_t* a, uint32_t b0, uint32_t b1) {
    asm volatile(
        "mma.sync.aligned.m16n8k16.row.col.f32.bf16.bf16.f32 "
        "{%0,%1,%2,%3}, {%4,%5,%6,%7}, {%8,%9}, {%0,%1,%2,%3};"
        : "+f"(c[0]), "+f"(c[1]), "+f"(c[2]), "+f"(c[3])
        : "r"(a[0]), "r"(a[1]), "r"(a[2]), "r"(a[3]), "r"(b0), "r"(b1));
}

// ---------------------------------------------------------------------------
// Fused kernel: grouped conv1 (+b1, pre-scaled by log2e) via mma.sync with
// bf16 hi/lo split, ELU (ex2-based, scale folded), dot W2*ln2, +b2, then the
// LAST CTA per 128-row tile L2-normalizes those rows (atomic-counter pattern).
// CTA = 128 rows x 8 groups, 256 threads = 8 warps; main loop barrier-free.
// ---------------------------------------------------------------------------
__global__ void __launch_bounds__(256)
div_encoder_fused(const float* __restrict__ x,
                  const float* __restrict__ W1,
                  const float* __restrict__ b1,
                  const float* __restrict__ W2,
                  const float* __restrict__ b2,
                  float* __restrict__ out)
{
    __shared__ uint4 Bsm[GCHUNK][8][32];   // [g][nt][lane] = {bh0,bh1,bl0,bl1} 32KB
    __shared__ float b1s[GCHUNK * U_MID];  // b1 * log2e
    __shared__ float w2s[GCHUNK * U_MID];  // W2 * ln2
    __shared__ float sout[GCHUNK][128];
    __shared__ unsigned int s_islast;

    const int tid   = threadIdx.x;
    const int wid   = tid >> 5;
    const int lane  = tid & 31;
    const int gbase = blockIdx.y * GCHUNK;
    const int rbase = blockIdx.x * 128;

    const int qr = lane >> 2;        // quad row id (0..7)
    const int qc = (lane & 3) * 2;   // quad col base (0,2,4,6)

    // ---- setup: warp w converts W1 group (gbase+w), scaled by log2e ----
    {
        const float* wg = W1 + (size_t)(gbase + wid) * (U_MID * V_IN);
        #pragma unroll
        for (int nt = 0; nt < 8; ++nt) {
            const int u = nt * 8 + qr;
            const float* wp = wg + u * V_IN;
            float2 p0 = *reinterpret_cast<const float2*>(wp + qc);
            float2 p1 = *reinterpret_cast<const float2*>(wp + qc + 8);
            uint32_t bh0, bl0, bh1, bl1;
            split2(p0.x * LOG2E, p0.y * LOG2E, bh0, bl0);
            split2(p1.x * LOG2E, p1.y * LOG2E, bh1, bl1);
            Bsm[wid][nt][lane] = make_uint4(bh0, bh1, bl0, bl1);
        }
        b1s[tid]       = b1[gbase * U_MID + tid]       * LOG2E;
        b1s[tid + 256] = b1[gbase * U_MID + tid + 256] * LOG2E;
        w2s[tid]       = W2[gbase * U_MID + tid]       * LN2F;
        w2s[tid + 256] = W2[gbase * U_MID + tid + 256] * LN2F;
    }
    __syncthreads();

    // ---- main loop: no barriers ----
    const int row0 = rbase + wid * 16 + qr;
    const float* xrow0 = x + (size_t)row0 * H_DIM + gbase * V_IN + qc;
    const float* xrow1 = xrow0 + (size_t)8 * H_DIM;

    for (int g = 0; g < GCHUNK; ++g) {
        // A fragments (quad-coalesced float2 loads, hi/lo bf16 split)
        uint32_t a_hi[4], a_lo[4];
        {
            const float* p = xrow0 + g * V_IN;
            const float* q = xrow1 + g * V_IN;
            float2 p00 = *reinterpret_cast<const float2*>(p);
            float2 p01 = *reinterpret_cast<const float2*>(p + 8);
            float2 p10 = *reinterpret_cast<const float2*>(q);
            float2 p11 = *reinterpret_cast<const float2*>(q + 8);
            split2(p00.x, p00.y, a_hi[0], a_lo[0]);
            split2(p10.x, p10.y, a_hi[1], a_lo[1]);
            split2(p01.x, p01.y, a_hi[2], a_lo[2]);
            split2(p11.x, p11.y, a_hi[3], a_lo[3]);
        }

        // accumulators pre-loaded with b1*log2e (column-constant)
        float c[8][4];
        #pragma unroll
        for (int nt = 0; nt < 8; ++nt) {
            float2 bb = *reinterpret_cast<const float2*>(&b1s[g * U_MID + nt * 8 + qc]);
            c[nt][0] = bb.x; c[nt][1] = bb.y; c[nt][2] = bb.x; c[nt][3] = bb.y;
        }

        #pragma unroll
        for (int nt = 0; nt < 8; ++nt) {
            uint4 B = Bsm[g][nt][lane];
            mma16816(c[nt], a_hi, B.x, B.y);   // hi*hi
            mma16816(c[nt], a_lo, B.x, B.y);   // lo*hi
            mma16816(c[nt], a_hi, B.z, B.w);   // hi*lo
        }

        // epilogue: v' = (h1+b1)*log2e.  elu-dot, scale folded:
        //   y += max(v', fma(ex2(min(v',0)), 1/ln2, -1/ln2)) * (w2*ln2)
        float y0a = 0.f, y0b = 0.f, y1a = 0.f, y1b = 0.f;
        #pragma unroll
        for (int nt = 0; nt < 8; ++nt) {
            float2 wv = *reinterpret_cast<const float2*>(&w2s[g * U_MID + nt * 8 + qc]);
            float e0 = ex2f(fminf(c[nt][0], 0.0f));
            float e1 = ex2f(fminf(c[nt][1], 0.0f));
            float e2 = ex2f(fminf(c[nt][2], 0.0f));
            float e3 = ex2f(fminf(c[nt][3], 0.0f));
            float r0 = fmaxf(c[nt][0], fmaf(e0, INV_LN2, N_INV_LN2));
            float r1 = fmaxf(c[nt][1], fmaf(e1, INV_LN2, N_INV_LN2));
            float r2 = fmaxf(c[nt][2], fmaf(e2, INV_LN2, N_INV_LN2));
            float r3 = fmaxf(c[nt][3], fmaf(e3, INV_LN2, N_INV_LN2));
            if (nt & 1) {
                y0b = fmaf(r0, wv.x, y0b);  y0b = fmaf(r1, wv.y, y0b);
                y1b = fmaf(r2, wv.x, y1b);  y1b = fmaf(r3, wv.y, y1b);
            } else {
                y0a = fmaf(r0, wv.x, y0a);  y0a = fmaf(r1, wv.y, y0a);
                y1a = fmaf(r2, wv.x, y1a);  y1a = fmaf(r3, wv.y, y1a);
            }
        }
        float y0 = y0a + y0b;
        float y1 = y1a + y1b;
        // reduce across the quad (cols split over lane&3)
        y0 += __shfl_xor_sync(0xFFFFFFFFu, y0, 1);
        y0 += __shfl_xor_sync(0xFFFFFFFFu, y0, 2);
        y1 += __shfl_xor_sync(0xFFFFFFFFu, y1, 1);
        y1 += __shfl_xor_sync(0xFFFFFFFFu, y1, 2);
        if ((lane & 3) == 0) {
            sout[g][wid * 16 + qr]     = y0;
            sout[g][wid * 16 + qr + 8] = y1;
        }
    }
    __syncthreads();

    // ---- coalesced output: 8 contiguous floats per row ----
    if (tid < 128) {
        const int row = rbase + tid;
        const float4* bp = reinterpret_cast<const float4*>(b2 + gbase);
        float4 b0 = bp[0], b1v = bp[1];
        float4 v0 = make_float4(sout[0][tid] + b0.x, sout[1][tid] + b0.y,
                                sout[2][tid] + b0.z, sout[3][tid] + b0.w);
        float4 v1 = make_float4(sout[4][tid] + b1v.x, sout[5][tid] + b1v.y,
                                sout[6][tid] + b1v.z, sout[7][tid] + b1v.w);
        float4* op = reinterpret_cast<float4*>(out + (size_t)row * D_GRP + gbase);
        op[0] = v0;
        op[1] = v1;
    }

    // ---- last CTA of this row tile normalizes its 128 rows ----
    __threadfence();
    __syncthreads();
    if (tid == 0) {
        unsigned int old = atomicAdd(&g_tile_ctr[blockIdx.x], 1u);
        unsigned int last = (old == gridDim.y - 1) ? 1u : 0u;
        if (last) g_tile_ctr[blockIdx.x] = 0u;   // reset for next graph replay
        s_islast = last;
    }
    __syncthreads();

    if (s_islast) {
        // 8 warps, warp handles rows rbase + (wid, wid+8, ..., wid+120)
        for (int r = wid; r < 128; r += 8) {
            float4* rp = reinterpret_cast<float4*>(out + (size_t)(rbase + r) * D_GRP);
            float4 v0 = rp[lane];
            float4 v1 = rp[lane + 32];
            float4 v2 = rp[lane + 64];
            float4 v3 = rp[lane + 96];
            float s = v0.x*v0.x + v0.y*v0.y + v0.z*v0.z + v0.w*v0.w
                    + v1.x*v1.x + v1.y*v1.y + v1.z*v1.z + v1.w*v1.w
                    + v2.x*v2.x + v2.y*v2.y + v2.z*v2.z + v2.w*v2.w
                    + v3.x*v3.x + v3.y*v3.y + v3.z*v3.z + v3.w*v3.w;
            #pragma unroll
            for (int off = 16; off > 0; off >>= 1)
                s += __shfl_xor_sync(0xFFFFFFFFu, s, off);
            const float scale = 1.0f / fmaxf(sqrtf(s), 1e-12f);
            v0.x *= scale; v0.y *= scale; v0.z *= scale; v0.w *= scale;
            v1.x *= scale; v1.y *= scale; v1.z *= scale; v1.w *= scale;
            v2.x *= scale; v2.y *= scale; v2.z *= scale; v2.w *= scale;
            v3.x *= scale; v3.y *= scale; v3.z *= scale; v3.w *= scale;
            rp[lane]      = v0;
            rp[lane + 32] = v1;
            rp[lane + 64] = v2;
            rp[lane + 96] = v3;
        }
    }
}

extern "C" void kernel_launch(void* const* d_in, const int* in_sizes, int n_in,
                              void* d_out, int out_size)
{
    const float* x  = (const float*)d_in[0];
    const float* W1 = (const float*)d_in[1];
    const float* b1 = (const float*)d_in[2];
    const float* W2 = (const float*)d_in[3];
    const float* b2 = (const float*)d_in[4];
    float* out = (float*)d_out;

    dim3 grid(N_ROWS / 128, D_GRP / GCHUNK);   // 32 x 64
    div_encoder_fused<<<grid, 256>>>(x, W1, b1, W2, b2, out);
}

// round 8
// speedup vs baseline: 1.1143x; 1.1143x over previous
#include <cuda_runtime.h>
#include <cuda_bf16.h>
#include <cstdint>

#define N_ROWS 4096
#define D_GRP  512
#define V_IN   16
#define U_MID  64
#define H_DIM  8192
#define GCHUNK 8          // groups per CTA

#define LOG2E     1.4426950408889634f
#define INV_LN2   1.4426950408889634f
#define N_INV_LN2 (-1.4426950408889634f)
#define LN2F      0.6931471805599453f

__device__ __forceinline__ float ex2f(float v) {
    float r; asm("ex2.approx.f32 %0, %1;" : "=f"(r) : "f"(v)); return r;
}
__device__ __forceinline__ uint32_t packbf2(float a, float b) {
    __nv_bfloat162 t = __floats2bfloat162_rn(a, b);
    return *reinterpret_cast<uint32_t*>(&t);
}
// split pair (a,b) into hi bf16x2 and exact-residual lo bf16x2
__device__ __forceinline__ void split2(float a, float b, uint32_t& hi, uint32_t& lo) {
    hi = packbf2(a, b);
    float ah = __uint_as_float(hi << 16);
    float bh = __uint_as_float(hi & 0xFFFF0000u);
    lo = packbf2(a - ah, b - bh);
}
// mma.m16n8k16 row.col bf16 -> fp32 accumulate in place
__device__ __forceinline__ void mma16816(float* c, const uint32_t* a, uint32_t b0, uint32_t b1) {
    asm volatile(
        "mma.sync.aligned.m16n8k16.row.col.f32.bf16.bf16.f32 "
        "{%0,%1,%2,%3}, {%4,%5,%6,%7}, {%8,%9}, {%0,%1,%2,%3};"
        : "+f"(c[0]), "+f"(c[1]), "+f"(c[2]), "+f"(c[3])
        : "r"(a[0]), "r"(a[1]), "r"(a[2]), "r"(a[3]), "r"(b0), "r"(b1));
}

// ---------------------------------------------------------------------------
// Main kernel: CTA = 128 rows x 8 groups, 256 threads = 8 warps, no barriers
// in the main loop. Per (warp, group, n-tile): 3x mma.m16n8k16 into a 4-reg
// accumulator (b1*log2e preloaded), then immediate ELU+dot(W2*ln2) epilogue —
// accumulator lifetime is one nt iteration, keeping regs low for occupancy.
// ---------------------------------------------------------------------------
__global__ void __launch_bounds__(256, 5)
div_encoder_main(const float* __restrict__ x,
                 const float* __restrict__ W1,
                 const float* __restrict__ b1,
                 const float* __restrict__ W2,
                 const float* __restrict__ b2,
                 float* __restrict__ out)
{
    __shared__ uint4 Bsm[GCHUNK][8][32];   // [g][nt][lane] = {bh0,bh1,bl0,bl1} 32KB
    __shared__ float b1s[GCHUNK * U_MID];  // b1 * log2e
    __shared__ float w2s[GCHUNK * U_MID];  // W2 * ln2
    __shared__ float sout[GCHUNK][128];

    const int tid   = threadIdx.x;
    const int wid   = tid >> 5;
    const int lane  = tid & 31;
    const int gbase = blockIdx.y * GCHUNK;
    const int rbase = blockIdx.x * 128;

    const int qr = lane >> 2;        // quad row id (0..7)
    const int qc = (lane & 3) * 2;   // quad col base (0,2,4,6)

    // ---- setup: warp w converts W1 group (gbase+w), scaled by log2e ----
    {
        const float* wg = W1 + (size_t)(gbase + wid) * (U_MID * V_IN);
        #pragma unroll
        for (int nt = 0; nt < 8; ++nt) {
            const int u = nt * 8 + qr;
            const float* wp = wg + u * V_IN;
            float2 p0 = *reinterpret_cast<const float2*>(wp + qc);
            float2 p1 = *reinterpret_cast<const float2*>(wp + qc + 8);
            uint32_t bh0, bl0, bh1, bl1;
            split2(p0.x * LOG2E, p0.y * LOG2E, bh0, bl0);
            split2(p1.x * LOG2E, p1.y * LOG2E, bh1, bl1);
            Bsm[wid][nt][lane] = make_uint4(bh0, bh1, bl0, bl1);
        }
        b1s[tid]       = b1[gbase * U_MID + tid]       * LOG2E;
        b1s[tid + 256] = b1[gbase * U_MID + tid + 256] * LOG2E;
        w2s[tid]       = W2[gbase * U_MID + tid]       * LN2F;
        w2s[tid + 256] = W2[gbase * U_MID + tid + 256] * LN2F;
    }
    __syncthreads();

    // ---- main loop: no barriers ----
    const int row0 = rbase + wid * 16 + qr;
    const float* xrow0 = x + (size_t)row0 * H_DIM + gbase * V_IN + qc;
    const float* xrow1 = xrow0 + (size_t)8 * H_DIM;

    for (int g = 0; g < GCHUNK; ++g) {
        // A fragments (quad-coalesced float2 loads, hi/lo bf16 split)
        uint32_t a_hi[4], a_lo[4];
        {
            const float* p = xrow0 + g * V_IN;
            const float* q = xrow1 + g * V_IN;
            float2 p00 = *reinterpret_cast<const float2*>(p);
            float2 p01 = *reinterpret_cast<const float2*>(p + 8);
            float2 p10 = *reinterpret_cast<const float2*>(q);
            float2 p11 = *reinterpret_cast<const float2*>(q + 8);
            split2(p00.x, p00.y, a_hi[0], a_lo[0]);
            split2(p10.x, p10.y, a_hi[1], a_lo[1]);
            split2(p01.x, p01.y, a_hi[2], a_lo[2]);
            split2(p11.x, p11.y, a_hi[3], a_lo[3]);
        }

        float y0a = 0.f, y0b = 0.f, y1a = 0.f, y1b = 0.f;

        #pragma unroll
        for (int nt = 0; nt < 8; ++nt) {
            // short-lived 4-reg accumulator, preloaded with b1*log2e
            float2 bb = *reinterpret_cast<const float2*>(&b1s[g * U_MID + nt * 8 + qc]);
            float c[4] = {bb.x, bb.y, bb.x, bb.y};

            uint4 B = Bsm[g][nt][lane];
            mma16816(c, a_hi, B.x, B.y);   // hi*hi
            mma16816(c, a_lo, B.x, B.y);   // lo*hi
            mma16816(c, a_hi, B.z, B.w);   // hi*lo

            // epilogue: v' = (h1+b1)*log2e;
            // y += max(v', fma(ex2(min(v',0)), 1/ln2, -1/ln2)) * (w2*ln2)
            float2 wv = *reinterpret_cast<const float2*>(&w2s[g * U_MID + nt * 8 + qc]);
            float e0 = ex2f(fminf(c[0], 0.0f));
            float e1 = ex2f(fminf(c[1], 0.0f));
            float e2 = ex2f(fminf(c[2], 0.0f));
            float e3 = ex2f(fminf(c[3], 0.0f));
            float r0 = fmaxf(c[0], fmaf(e0, INV_LN2, N_INV_LN2));
            float r1 = fmaxf(c[1], fmaf(e1, INV_LN2, N_INV_LN2));
            float r2 = fmaxf(c[2], fmaf(e2, INV_LN2, N_INV_LN2));
            float r3 = fmaxf(c[3], fmaf(e3, INV_LN2, N_INV_LN2));
            if (nt & 1) {
                y0b = fmaf(r0, wv.x, y0b);  y0b = fmaf(r1, wv.y, y0b);
                y1b = fmaf(r2, wv.x, y1b);  y1b = fmaf(r3, wv.y, y1b);
            } else {
                y0a = fmaf(r0, wv.x, y0a);  y0a = fmaf(r1, wv.y, y0a);
                y1a = fmaf(r2, wv.x, y1a);  y1a = fmaf(r3, wv.y, y1a);
            }
        }

        float y0 = y0a + y0b;
        float y1 = y1a + y1b;
        // reduce across the quad (cols split over lane&3)
        y0 += __shfl_xor_sync(0xFFFFFFFFu, y0, 1);
        y0 += __shfl_xor_sync(0xFFFFFFFFu, y0, 2);
        y1 += __shfl_xor_sync(0xFFFFFFFFu, y1, 1);
        y1 += __shfl_xor_sync(0xFFFFFFFFu, y1, 2);
        if ((lane & 3) == 0) {
            sout[g][wid * 16 + qr]     = y0;
            sout[g][wid * 16 + qr + 8] = y1;
        }
    }
    __syncthreads();

    // ---- coalesced output: 8 contiguous floats per row ----
    if (tid < 128) {
        const int row = rbase + tid;
        const float4* bp = reinterpret_cast<const float4*>(b2 + gbase);
        float4 b0 = bp[0], b1v = bp[1];
        float4 v0 = make_float4(sout[0][tid] + b0.x, sout[1][tid] + b0.y,
                                sout[2][tid] + b0.z, sout[3][tid] + b0.w);
        float4 v1 = make_float4(sout[4][tid] + b1v.x, sout[5][tid] + b1v.y,
                                sout[6][tid] + b1v.z, sout[7][tid] + b1v.w);
        float4* op = reinterpret_cast<float4*>(out + (size_t)row * D_GRP + gbase);
        op[0] = v0;
        op[1] = v1;
    }
}

// ---------------------------------------------------------------------------
// Row L2 normalize, one warp per row.
// ---------------------------------------------------------------------------
__global__ void __launch_bounds__(256)
div_encoder_norm(float* __restrict__ y)
{
    const int row  = blockIdx.x * 8 + (threadIdx.x >> 5);
    const int lane = threadIdx.x & 31;
    float4* rp = reinterpret_cast<float4*>(y + (size_t)row * D_GRP);

    float4 v0 = rp[lane];
    float4 v1 = rp[lane + 32];
    float4 v2 = rp[lane + 64];
    float4 v3 = rp[lane + 96];

    float s = v0.x*v0.x + v0.y*v0.y + v0.z*v0.z + v0.w*v0.w
            + v1.x*v1.x + v1.y*v1.y + v1.z*v1.z + v1.w*v1.w
            + v2.x*v2.x + v2.y*v2.y + v2.z*v2.z + v2.w*v2.w
            + v3.x*v3.x + v3.y*v3.y + v3.z*v3.z + v3.w*v3.w;

    #pragma unroll
    for (int off = 16; off > 0; off >>= 1)
        s += __shfl_xor_sync(0xFFFFFFFFu, s, off);

    const float scale = 1.0f / fmaxf(sqrtf(s), 1e-12f);
    v0.x *= scale; v0.y *= scale; v0.z *= scale; v0.w *= scale;
    v1.x *= scale; v1.y *= scale; v1.z *= scale; v1.w *= scale;
    v2.x *= scale; v2.y *= scale; v2.z *= scale; v2.w *= scale;
    v3.x *= scale; v3.y *= scale; v3.z *= scale; v3.w *= scale;
    rp[lane]      = v0;
    rp[lane + 32] = v1;
    rp[lane + 64] = v2;
    rp[lane + 96] = v3;
}

extern "C" void kernel_launch(void* const* d_in, const int* in_sizes, int n_in,
                              void* d_out, int out_size)
{
    const float* x  = (const float*)d_in[0];
    const float* W1 = (const float*)d_in[1];
    const float* b1 = (const float*)d_in[2];
    const float* W2 = (const float*)d_in[3];
    const float* b2 = (const float*)d_in[4];
    float* out = (float*)d_out;

    dim3 grid(N_ROWS / 128, D_GRP / GCHUNK);   // 32 x 64
    div_encoder_main<<<grid, 256>>>(x, W1, b1, W2, b2, out);
    div_encoder_norm<<<N_ROWS / 8, 256>>>(out);
}

// round 9
// speedup vs baseline: 1.1467x; 1.0290x over previous
#include <cuda_runtime.h>
#include <cuda_bf16.h>
#include <cstdint>

#define N_ROWS 4096
#define D_GRP  512
#define V_IN   16
#define U_MID  64
#define H_DIM  8192
#define GCHUNK 8          // groups per CTA

#define LOG2E     1.4426950408889634f
#define INV_LN2   1.4426950408889634f
#define N_INV_LN2 (-1.4426950408889634f)
#define LN2F      0.6931471805599453f

__device__ __forceinline__ float ex2f(float v) {
    float r; asm("ex2.approx.f32 %0, %1;" : "=f"(r) : "f"(v)); return r;
}
__device__ __forceinline__ uint32_t packbf2(float a, float b) {
    __nv_bfloat162 t = __floats2bfloat162_rn(a, b);
    return *reinterpret_cast<uint32_t*>(&t);
}
// split pair (a,b) into hi bf16x2 and exact-residual lo bf16x2
__device__ __forceinline__ void split2(float a, float b, uint32_t& hi, uint32_t& lo) {
    hi = packbf2(a, b);
    float ah = __uint_as_float(hi << 16);
    float bh = __uint_as_float(hi & 0xFFFF0000u);
    lo = packbf2(a - ah, b - bh);
}
// streaming float2 load (evict-first: x has no reuse)
__device__ __forceinline__ float2 ldcs2(const float* p) {
    float2 v;
    asm volatile("ld.global.cs.v2.f32 {%0,%1}, [%2];" : "=f"(v.x), "=f"(v.y) : "l"(p));
    return v;
}
// mma.m16n8k16 row.col bf16 -> fp32 accumulate in place
__device__ __forceinline__ void mma16816(float* c, const uint32_t* a, uint32_t b0, uint32_t b1) {
    asm volatile(
        "mma.sync.aligned.m16n8k16.row.col.f32.bf16.bf16.f32 "
        "{%0,%1,%2,%3}, {%4,%5,%6,%7}, {%8,%9}, {%0,%1,%2,%3};"
        : "+f"(c[0]), "+f"(c[1]), "+f"(c[2]), "+f"(c[3])
        : "r"(a[0]), "r"(a[1]), "r"(a[2]), "r"(a[3]), "r"(b0), "r"(b1));
}

// ---------------------------------------------------------------------------
// Main kernel: CTA = 128 rows x 8 groups, 256 threads = 8 warps, no barriers
// in the main loop. x loads for group g+1 are issued right after group g's
// fragments are built (register double-buffer), so the ~200-instruction
// nt-loop hides the streaming DRAM latency.
// ---------------------------------------------------------------------------
__global__ void __launch_bounds__(256)
div_encoder_main(const float* __restrict__ x,
                 const float* __restrict__ W1,
                 const float* __restrict__ b1,
                 const float* __restrict__ W2,
                 const float* __restrict__ b2,
                 float* __restrict__ out)
{
    __shared__ uint4 Bsm[GCHUNK][8][32];   // [g][nt][lane] = {bh0,bh1,bl0,bl1} 32KB
    __shared__ float b1s[GCHUNK * U_MID];  // b1 * log2e
    __shared__ float w2s[GCHUNK * U_MID];  // W2 * ln2
    __shared__ float sout[GCHUNK][128];

    const int tid   = threadIdx.x;
    const int wid   = tid >> 5;
    const int lane  = tid & 31;
    const int gbase = blockIdx.y * GCHUNK;
    const int rbase = blockIdx.x * 128;

    const int qr = lane >> 2;        // quad row id (0..7)
    const int qc = (lane & 3) * 2;   // quad col base (0,2,4,6)

    // ---- setup: warp w converts W1 group (gbase+w), scaled by log2e ----
    {
        const float* wg = W1 + (size_t)(gbase + wid) * (U_MID * V_IN);
        #pragma unroll
        for (int nt = 0; nt < 8; ++nt) {
            const int u = nt * 8 + qr;
            const float* wp = wg + u * V_IN;
            float2 p0 = *reinterpret_cast<const float2*>(wp + qc);
            float2 p1 = *reinterpret_cast<const float2*>(wp + qc + 8);
            uint32_t bh0, bl0, bh1, bl1;
            split2(p0.x * LOG2E, p0.y * LOG2E, bh0, bl0);
            split2(p1.x * LOG2E, p1.y * LOG2E, bh1, bl1);
            Bsm[wid][nt][lane] = make_uint4(bh0, bh1, bl0, bl1);
        }
        b1s[tid]       = b1[gbase * U_MID + tid]       * LOG2E;
        b1s[tid + 256] = b1[gbase * U_MID + tid + 256] * LOG2E;
        w2s[tid]       = W2[gbase * U_MID + tid]       * LN2F;
        w2s[tid + 256] = W2[gbase * U_MID + tid + 256] * LN2F;
    }
    __syncthreads();

    // ---- main loop: barrier-free, x double-buffered in registers ----
    const int row0 = rbase + wid * 16 + qr;
    const float* xrow0 = x + (size_t)row0 * H_DIM + gbase * V_IN + qc;
    const float* xrow1 = xrow0 + (size_t)8 * H_DIM;

    float2 xb0, xb1, xb2, xb3;                 // current group's raw x
    xb0 = ldcs2(xrow0);       xb1 = ldcs2(xrow0 + 8);
    xb2 = ldcs2(xrow1);       xb3 = ldcs2(xrow1 + 8);

    for (int g = 0; g < GCHUNK; ++g) {
        // build A fragments from the buffered registers
        uint32_t a_hi[4], a_lo[4];
        split2(xb0.x, xb0.y, a_hi[0], a_lo[0]);
        split2(xb2.x, xb2.y, a_hi[1], a_lo[1]);
        split2(xb1.x, xb1.y, a_hi[2], a_lo[2]);
        split2(xb3.x, xb3.y, a_hi[3], a_lo[3]);

        // prefetch next group's x — hidden under the nt loop below
        if (g + 1 < GCHUNK) {
            const float* p = xrow0 + (g + 1) * V_IN;
            const float* q = xrow1 + (g + 1) * V_IN;
            xb0 = ldcs2(p);       xb1 = ldcs2(p + 8);
            xb2 = ldcs2(q);       xb3 = ldcs2(q + 8);
        }

        float y0a = 0.f, y0b = 0.f, y1a = 0.f, y1b = 0.f;

        #pragma unroll
        for (int nt = 0; nt < 8; ++nt) {
            // short-lived 4-reg accumulator, preloaded with b1*log2e
            float2 bb = *reinterpret_cast<const float2*>(&b1s[g * U_MID + nt * 8 + qc]);
            float c[4] = {bb.x, bb.y, bb.x, bb.y};

            uint4 B = Bsm[g][nt][lane];
            mma16816(c, a_hi, B.x, B.y);   // hi*hi
            mma16816(c, a_lo, B.x, B.y);   // lo*hi
            mma16816(c, a_hi, B.z, B.w);   // hi*lo

            // epilogue: v' = (h1+b1)*log2e;
            // y += max(v', fma(ex2(min(v',0)), 1/ln2, -1/ln2)) * (w2*ln2)
            float2 wv = *reinterpret_cast<const float2*>(&w2s[g * U_MID + nt * 8 + qc]);
            float e0 = ex2f(fminf(c[0], 0.0f));
            float e1 = ex2f(fminf(c[1], 0.0f));
            float e2 = ex2f(fminf(c[2], 0.0f));
            float e3 = ex2f(fminf(c[3], 0.0f));
            float r0 = fmaxf(c[0], fmaf(e0, INV_LN2, N_INV_LN2));
            float r1 = fmaxf(c[1], fmaf(e1, INV_LN2, N_INV_LN2));
            float r2 = fmaxf(c[2], fmaf(e2, INV_LN2, N_INV_LN2));
            float r3 = fmaxf(c[3], fmaf(e3, INV_LN2, N_INV_LN2));
            if (nt & 1) {
                y0b = fmaf(r0, wv.x, y0b);  y0b = fmaf(r1, wv.y, y0b);
                y1b = fmaf(r2, wv.x, y1b);  y1b = fmaf(r3, wv.y, y1b);
            } else {
                y0a = fmaf(r0, wv.x, y0a);  y0a = fmaf(r1, wv.y, y0a);
                y1a = fmaf(r2, wv.x, y1a);  y1a = fmaf(r3, wv.y, y1a);
            }
        }

        float y0 = y0a + y0b;
        float y1 = y1a + y1b;
        // reduce across the quad (cols split over lane&3)
        y0 += __shfl_xor_sync(0xFFFFFFFFu, y0, 1);
        y0 += __shfl_xor_sync(0xFFFFFFFFu, y0, 2);
        y1 += __shfl_xor_sync(0xFFFFFFFFu, y1, 1);
        y1 += __shfl_xor_sync(0xFFFFFFFFu, y1, 2);
        if ((lane & 3) == 0) {
            sout[g][wid * 16 + qr]     = y0;
            sout[g][wid * 16 + qr + 8] = y1;
        }
    }
    __syncthreads();

    // ---- coalesced output: 8 contiguous floats per row ----
    if (tid < 128) {
        const int row = rbase + tid;
        const float4* bp = reinterpret_cast<const float4*>(b2 + gbase);
        float4 b0 = bp[0], b1v = bp[1];
        float4 v0 = make_float4(sout[0][tid] + b0.x, sout[1][tid] + b0.y,
                                sout[2][tid] + b0.z, sout[3][tid] + b0.w);
        float4 v1 = make_float4(sout[4][tid] + b1v.x, sout[5][tid] + b1v.y,
                                sout[6][tid] + b1v.z, sout[7][tid] + b1v.w);
        float4* op = reinterpret_cast<float4*>(out + (size_t)row * D_GRP + gbase);
        op[0] = v0;
        op[1] = v1;
    }
}

// ---------------------------------------------------------------------------
// Row L2 normalize: one warp per TWO rows (8 loads in flight -> better MLP).
// Block 256 = 8 warps = 16 rows; grid = N/16 = 256.
// ---------------------------------------------------------------------------
__global__ void __launch_bounds__(256)
div_encoder_norm(float* __restrict__ y)
{
    const int wid  = threadIdx.x >> 5;
    const int lane = threadIdx.x & 31;
    const int r0   = blockIdx.x * 16 + wid * 2;

    float4* ra = reinterpret_cast<float4*>(y + (size_t)r0 * D_GRP);
    float4* rb = reinterpret_cast<float4*>(y + (size_t)(r0 + 1) * D_GRP);

    float4 a0 = ra[lane], a1 = ra[lane + 32], a2 = ra[lane + 64], a3 = ra[lane + 96];
    float4 b0 = rb[lane], b1 = rb[lane + 32], b2 = rb[lane + 64], b3 = rb[lane + 96];

    float sa = a0.x*a0.x + a0.y*a0.y + a0.z*a0.z + a0.w*a0.w
             + a1.x*a1.x + a1.y*a1.y + a1.z*a1.z + a1.w*a1.w
             + a2.x*a2.x + a2.y*a2.y + a2.z*a2.z + a2.w*a2.w
             + a3.x*a3.x + a3.y*a3.y + a3.z*a3.z + a3.w*a3.w;
    float sb = b0.x*b0.x + b0.y*b0.y + b0.z*b0.z + b0.w*b0.w
             + b1.x*b1.x + b1.y*b1.y + b1.z*b1.z + b1.w*b1.w
             + b2.x*b2.x + b2.y*b2.y + b2.z*b2.z + b2.w*b2.w
             + b3.x*b3.x + b3.y*b3.y + b3.z*b3.z + b3.w*b3.w;

    #pragma unroll
    for (int off = 16; off > 0; off >>= 1) {
        sa += __shfl_xor_sync(0xFFFFFFFFu, sa, off);
        sb += __shfl_xor_sync(0xFFFFFFFFu, sb, off);
    }

    const float ka = 1.0f / fmaxf(sqrtf(sa), 1e-12f);
    const float kb = 1.0f / fmaxf(sqrtf(sb), 1e-12f);
    a0.x *= ka; a0.y *= ka; a0.z *= ka; a0.w *= ka;
    a1.x *= ka; a1.y *= ka; a1.z *= ka; a1.w *= ka;
    a2.x *= ka; a2.y *= ka; a2.z *= ka; a2.w *= ka;
    a3.x *= ka; a3.y *= ka; a3.z *= ka; a3.w *= ka;
    b0.x *= kb; b0.y *= kb; b0.z *= kb; b0.w *= kb;
    b1.x *= kb; b1.y *= kb; b1.z *= kb; b1.w *= kb;
    b2.x *= kb; b2.y *= kb; b2.z *= kb; b2.w *= kb;
    b3.x *= kb; b3.y *= kb; b3.z *= kb; b3.w *= kb;
    ra[lane]      = a0;  ra[lane + 32] = a1;  ra[lane + 64] = a2;  ra[lane + 96] = a3;
    rb[lane]      = b0;  rb[lane + 32] = b1;  rb[lane + 64] = b2;  rb[lane + 96] = b3;
}

extern "C" void kernel_launch(void* const* d_in, const int* in_sizes, int n_in,
                              void* d_out, int out_size)
{
    const float* x  = (const float*)d_in[0];
    const float* W1 = (const float*)d_in[1];
    const float* b1 = (const float*)d_in[2];
    const float* W2 = (const float*)d_in[3];
    const float* b2 = (const float*)d_in[4];
    float* out = (float*)d_out;

    dim3 grid(N_ROWS / 128, D_GRP / GCHUNK);   // 32 x 64
    div_encoder_main<<<grid, 256>>>(x, W1, b1, W2, b2, out);
    div_encoder_norm<<<N_ROWS / 16, 256>>>(out);
}